// round 2
// baseline (speedup 1.0000x reference)
#include <cuda_runtime.h>
#include <math.h>

#define BB 4
#define LL 2048
#define DD 64
#define CHUNK 32
#define NCHUNK (LL / CHUNK)   // 64

// Scratch (no cudaMalloc allowed) — fully overwritten every launch, graph-replay safe.
__device__ float g_csum[BB][NCHUNK][DD];   // per-chunk sum of e_j * exp(ab*t_j)
__device__ float g_esum[BB][NCHUNK][DD];   // per-chunk sum of e_j
__device__ float g_vsum[BB][NCHUNK][DD];   // per-chunk sum of e_j * (1-exp(-ab*(tlast-t_j)))
__device__ float g_usum[BB][NCHUNK];       // per-chunk sum of |u|
__device__ float g_pbase[BB][NCHUNK][DD];  // exclusive scan of g_csum across chunks
__device__ float g_base[BB];               // E_tot·V_tot + horizon*U_tot
__device__ float g_cout[BB][NCHUNK];       // per-chunk sum of -log(lam)

// ---------------- Kernel A: per-chunk partials ----------------
__global__ void kA(const int* __restrict__ ids, const float* __restrict__ times,
                   const float* __restrict__ emb, const float* __restrict__ u_table,
                   const float* __restrict__ beta) {
    const int bc = blockIdx.x;
    const int b  = bc / NCHUNK, c = bc % NCHUNK;
    const int d  = threadIdx.x;            // 0..63
    __shared__ int   sid[CHUNK];
    __shared__ float st[CHUNK];
    const float ab = fabsf(beta[0]);
    const int base = b * LL + c * CHUNK;
    if (d < CHUNK) {
        int id = ids[base + d];
        sid[d] = id;
        st[d]  = times[base + d] * 1e-4f;
    }
    __syncthreads();
    const float tlast = times[b * LL + LL - 1] * 1e-4f;
    float cs = 0.f, es = 0.f, vs = 0.f;
#pragma unroll 8
    for (int j = 0; j < CHUNK; ++j) {
        float e  = emb[(long)sid[j] * DD + d];
        float tj = st[j];
        cs = fmaf(e, __expf(ab * tj), cs);
        es += e;
        vs = fmaf(e, 1.f - __expf(-ab * (tlast - tj)), vs);
    }
    g_csum[b][c][d] = cs;
    g_esum[b][c][d] = es;
    g_vsum[b][c][d] = vs;
    if (d == 0) {
        float u = 0.f;
#pragma unroll 8
        for (int j = 0; j < CHUNK; ++j) u += fabsf(u_table[sid[j]]);
        g_usum[b][c] = u;
    }
}

// ---------------- Kernel B: cross-chunk exclusive scan + base term ----------------
__global__ void kB(const float* __restrict__ times) {
    const int b = blockIdx.x;
    const int d = threadIdx.x;             // 0..63
    float p = 0.f, Et = 0.f, Vt = 0.f;
    for (int c = 0; c < NCHUNK; ++c) {
        g_pbase[b][c][d] = p;
        p  += g_csum[b][c][d];
        Et += g_esum[b][c][d];
        Vt += g_vsum[b][c][d];
    }
    __shared__ float sred[DD];
    sred[d] = Et * Vt;
    __syncthreads();
    if (d == 0) {
        float ev = 0.f;
        for (int i = 0; i < DD; ++i) ev += sred[i];
        float ut = 0.f;
        for (int c = 0; c < NCHUNK; ++c) ut += g_usum[b][c];
        float horizon = (times[b * LL + LL - 1] - times[b * LL + 1]) * 1e-4f;
        g_base[b] = ev + horizon * ut;
    }
}

// ---------------- Kernel C: within-chunk serial scan (one warp per chunk) ----------------
__global__ void kC(const int* __restrict__ ids, const float* __restrict__ times,
                   const float* __restrict__ emb, const float* __restrict__ u_table,
                   const float* __restrict__ beta) {
    const int bc = blockIdx.x;
    const int b  = bc / NCHUNK, c = bc % NCHUNK;
    const int t  = threadIdx.x;            // 0..31 ; owns dims t and t+32
    __shared__ int   sid[CHUNK];
    __shared__ float st[CHUNK];
    __shared__ float su[CHUNK];
    const float ab = fabsf(beta[0]);
    const int base = b * LL + c * CHUNK;
    {
        int id = ids[base + t];
        sid[t] = id;
        st[t]  = times[base + t] * 1e-4f;
        su[t]  = fabsf(u_table[id]);
    }
    __syncwarp();
    float P0 = g_pbase[b][c][t];
    float P1 = g_pbase[b][c][t + 32];
    float acc = 0.f;
    for (int j = 0; j < CHUNK; ++j) {
        int   id = sid[j];
        float tj = st[j];
        float e0 = emb[(long)id * DD + t];
        float e1 = emb[(long)id * DD + t + 32];
        // dot(e_i, P_{<i})  — strict lower triangle: dot BEFORE updating P
        float dp = e0 * P0 + e1 * P1;
#pragma unroll
        for (int o = 16; o > 0; o >>= 1) dp += __shfl_xor_sync(0xffffffffu, dp, o);
        float s1  = ab * __expf(-ab * tj) * dp;
        float lam = fabsf(s1 + su[j]) + 1e-6f;
        acc -= logf(lam);
        float w = __expf(ab * tj);
        P0 = fmaf(e0, w, P0);
        P1 = fmaf(e1, w, P1);
    }
    if (t == 0) g_cout[b][c] = acc;        // no atomics -> deterministic
}

// ---------------- Kernel D: deterministic final reduction ----------------
__global__ void kD(float* __restrict__ out) {
    const int b = blockIdx.x;
    const int t = threadIdx.x;             // 0..63
    __shared__ float sred[NCHUNK];
    sred[t] = g_cout[b][t];
    __syncthreads();
    if (t == 0) {
        float s = 0.f;
        for (int c = 0; c < NCHUNK; ++c) s += sred[c];
        out[b] = s + g_base[b];
    }
}

extern "C" void kernel_launch(void* const* d_in, const int* in_sizes, int n_in,
                              void* d_out, int out_size) {
    const int*   ids   = (const int*)  d_in[0];
    const float* times = (const float*)d_in[1];
    // d_in[2] = mask (all ones, unused)
    const float* emb   = (const float*)d_in[3];
    const float* ut    = (const float*)d_in[4];
    const float* beta  = (const float*)d_in[5];
    float* out = (float*)d_out;

    kA<<<BB * NCHUNK, DD>>>(ids, times, emb, ut, beta);
    kB<<<BB, DD>>>(times);
    kC<<<BB * NCHUNK, 32>>>(ids, times, emb, ut, beta);
    kD<<<BB, NCHUNK>>>(out);
}

// round 3
// speedup vs baseline: 1.3798x; 1.3798x over previous
#include <cuda_runtime.h>
#include <math.h>

#define BB 4
#define LL 2048
#define DD 64
#define CHUNK 32
#define NCHUNK (LL / CHUNK)   // 64

// Scratch (no cudaMalloc allowed) — overwritten every launch.
__device__ float g_csum[BB][NCHUNK][DD];   // per-chunk sum of e_j * exp(ab*t_j)
__device__ float g_esum[BB][NCHUNK][DD];   // per-chunk sum of e_j
__device__ float g_vsum[BB][NCHUNK][DD];   // per-chunk sum of e_j * (1-exp(-ab*(tlast-t_j)))
__device__ float g_usum[BB][NCHUNK];       // per-chunk sum of |u|
__device__ float g_accv[BB][NCHUNK];       // per-chunk sum of -log(lam)
__device__ float g_base[BB];               // Et·Vt + horizon*Ut
__device__ int   g_cnt[2 * BB];            // [0..3]=gather done, [4..7]=acc done (memset to 0 per launch)

__device__ __forceinline__ float warp_sum(float v) {
#pragma unroll
    for (int o = 16; o > 0; o >>= 1) v += __shfl_xor_sync(0xffffffffu, v, o);
    return v;
}

__device__ __forceinline__ float dot4(float4 a, float4 b, float acc) {
    acc = fmaf(a.x, b.x, acc);
    acc = fmaf(a.y, b.y, acc);
    acc = fmaf(a.z, b.z, acc);
    acc = fmaf(a.w, b.w, acc);
    return acc;
}

__global__ __launch_bounds__(128) void hawkes_fused(
    const int* __restrict__ ids, const float* __restrict__ times,
    const float* __restrict__ emb, const float* __restrict__ u_table,
    const float* __restrict__ beta, float* __restrict__ out)
{
    const int bc   = blockIdx.x;
    const int b    = bc >> 6;          // batch
    const int c    = bc & 63;          // chunk
    const int tid  = threadIdx.x;
    const int lane = tid & 31;
    const int warp = tid >> 5;

    __shared__ float sE[CHUNK][68];              // E rows, padded (68%4==0 for float4, 68 odd/16-stride conflict-free)
    __shared__ float sw[CHUNK];                  // exp(ab*t_j)
    __shared__ float sme[CHUNK];                 // exp(-ab*t_j)
    __shared__ float svw[CHUNK];                 // 1 - exp(-ab*(tlast-t_j))
    __shared__ float su[CHUNK];                  // |u_j|
    __shared__ float spb[DD];                    // exclusive cross-chunk prefix P
    __shared__ float sP[4][CHUNK];               // phase-C d-slice partials
    __shared__ float sb0[DD], sb1[DD], sb2[DD];  // combine buffers
    __shared__ float sred[DD];                   // reductions
    __shared__ int   sid[CHUNK];
    __shared__ int   slast;

    const float ab    = fabsf(beta[0]);
    const int   base  = b * LL + c * CHUNK;
    const float tlast = times[b * LL + LL - 1] * 1e-4f;

    // ---- init: ids, times, per-event scalars ----
    if (tid < CHUNK) {
        int id = ids[base + tid];
        sid[tid] = id;
        float tj = times[base + tid] * 1e-4f;
        float w  = __expf(ab * tj);
        sw[tid]  = w;
        sme[tid] = __expf(-ab * tj);
        svw[tid] = 1.0f - __expf(-ab * tlast) * w;
        su[tid]  = fabsf(u_table[id]);
    }
    __syncthreads();

    // ---- gather E + per-chunk sums (thread = (d, g), g-half of j range) ----
    const int d = tid & 63, g = tid >> 6;
    float cs = 0.f, es = 0.f, vs = 0.f;
#pragma unroll
    for (int jj = 0; jj < 16; ++jj) {
        int j = g * 16 + jj;
        float e = emb[(long)sid[j] * DD + d];
        sE[j][d] = e;
        cs = fmaf(e, sw[j], cs);
        es += e;
        vs = fmaf(e, svw[j], vs);
    }
    if (g == 1) { sb0[d] = cs; sb1[d] = es; sb2[d] = vs; }
    __syncthreads();
    if (g == 0) {
        g_csum[b][c][d] = cs + sb0[d];
        g_esum[b][c][d] = es + sb1[d];
        g_vsum[b][c][d] = vs + sb2[d];
    }
    if (warp == 0) {
        float uv = warp_sum(su[lane]);
        if (lane == 0) g_usum[b][c] = uv;
    }

    // ---- publish + device-wide sync (all 256 blocks co-resident in wave 1) ----
    __threadfence();
    __syncthreads();
    if (tid == 0) {
        atomicAdd(&g_cnt[b], 1);
        int v;
        do {
            asm volatile("ld.acquire.gpu.u32 %0, [%1];" : "=r"(v) : "l"(&g_cnt[b]) : "memory");
        } while (v < NCHUNK);
    }
    __syncthreads();

    // ---- own exclusive prefix across earlier chunks (parity-split over g) ----
    {
        float p = 0.f;
#pragma unroll 4
        for (int cp = g; cp < c; cp += 2) p += __ldcg(&g_csum[b][cp][d]);
        if (g == 1) sb0[d] = p;
        __syncthreads();
        if (g == 0) spb[d] = p + sb0[d];
    }

    // ---- block (b,0): integral/base term (its prefix is trivially zero) ----
    if (c == 0) {
        float et = 0.f, vt = 0.f;
#pragma unroll 4
        for (int cp = g; cp < NCHUNK; cp += 2) {
            et += __ldcg(&g_esum[b][cp][d]);
            vt += __ldcg(&g_vsum[b][cp][d]);
        }
        if (g == 1) { sb1[d] = et; sb2[d] = vt; }
        __syncthreads();
        if (g == 0) sred[d] = (et + sb1[d]) * (vt + sb2[d]);
        __syncthreads();
        if (tid == 0) {
            float ev = 0.f;
            for (int k = 0; k < DD; ++k) ev += sred[k];
            float ut = 0.f;
            for (int k = 0; k < NCHUNK; ++k) ut += __ldcg(&g_usum[b][k]);
            float horizon = (times[b * LL + LL - 1] - times[b * LL + 1]) * 1e-4f;
            g_base[b] = ev + horizon * ut;
        }
    }
    __syncthreads();   // spb (and for c==0, g_base) ready

    // ---- phase C: dp_i = e_i·P + sum_{j<i} w_j (e_i·e_j), 4 warps = 4 D-slices ----
    {
        const int i = lane, q = warp;
        const float4* erow = reinterpret_cast<const float4*>(&sE[i][0]) + q * 4;
        float4 a0 = erow[0], a1 = erow[1], a2 = erow[2], a3 = erow[3];
        const float4* pb = reinterpret_cast<const float4*>(spb) + q * 4;
        float part = 0.f;
        part = dot4(a0, pb[0], part);
        part = dot4(a1, pb[1], part);
        part = dot4(a2, pb[2], part);
        part = dot4(a3, pb[3], part);
#pragma unroll
        for (int j = 0; j < CHUNK; ++j) {
            const float4* ej = reinterpret_cast<const float4*>(&sE[j][0]) + q * 4;
            float s = 0.f;
            s = dot4(a0, ej[0], s);
            s = dot4(a1, ej[1], s);
            s = dot4(a2, ej[2], s);
            s = dot4(a3, ej[3], s);
            if (j < i) part = fmaf(sw[j], s, part);   // strict lower triangle
        }
        sP[q][i] = part;
    }
    __syncthreads();
    if (warp == 0) {
        float dp  = sP[0][lane] + sP[1][lane] + sP[2][lane] + sP[3][lane];
        float s1  = ab * sme[lane] * dp;
        float lam = fabsf(s1 + su[lane]) + 1e-6f;
        float v   = -__logf(lam);
        v = warp_sum(v);
        if (lane == 0) g_accv[b][c] = v;
    }

    // ---- last block per batch does the deterministic final reduction ----
    __threadfence();
    __syncthreads();
    if (tid == 0) {
        int done = atomicAdd(&g_cnt[BB + b], 1);
        slast = (done == NCHUNK - 1) ? 1 : 0;
    }
    __syncthreads();
    if (slast) {
        if (tid < NCHUNK) sred[tid] = __ldcg(&g_accv[b][tid]);
        __syncthreads();
        if (tid == 0) {
            float s = 0.f;
            for (int k = 0; k < NCHUNK; ++k) s += sred[k];   // fixed order -> deterministic
            out[b] = s + __ldcg(&g_base[b]);
        }
    }
}

extern "C" void kernel_launch(void* const* d_in, const int* in_sizes, int n_in,
                              void* d_out, int out_size) {
    const int*   ids   = (const int*)  d_in[0];
    const float* times = (const float*)d_in[1];
    // d_in[2] = mask (all ones, unused)
    const float* emb   = (const float*)d_in[3];
    const float* ut    = (const float*)d_in[4];
    const float* beta  = (const float*)d_in[5];
    float* out = (float*)d_out;

    void* cntp = nullptr;
    cudaGetSymbolAddress(&cntp, g_cnt);
    cudaMemsetAsync(cntp, 0, sizeof(int) * 2 * BB);   // reset counters (graph-capturable)
    hawkes_fused<<<BB * NCHUNK, 128>>>(ids, times, emb, ut, beta, out);
}

// round 4
// speedup vs baseline: 1.4451x; 1.0473x over previous
#include <cuda_runtime.h>
#include <math.h>

#define BB 4
#define LL 2048
#define DD 64
#define CHUNK 32
#define NCHUNK (LL / CHUNK)   // 64

// Scratch (no cudaMalloc allowed). Flags/counters are monotonic across launches (never reset).
__device__ float g_csum[BB][NCHUNK][DD];   // per-chunk sum of e_j * exp(ab*t_j)
__device__ float g_esum[BB][NCHUNK][DD];   // per-chunk sum of e_j
__device__ float g_vsum[BB][NCHUNK][DD];   // per-chunk sum of e_j * (1-exp(-ab*(tlast-t_j)))
__device__ float g_usum[BB][NCHUNK];       // per-chunk sum of |u|
__device__ float g_accv[BB][NCHUNK];       // per-chunk sum of -log(lam)
__device__ float g_base[BB];               // Et·Vt + horizon*Ut
__device__ int   g_flagA[BB][NCHUNK];      // publish flags; +1 per launch, launch-relative
__device__ int   g_cntB[BB];               // completion tickets; +64 per launch

__device__ __forceinline__ float warp_sum(float v) {
#pragma unroll
    for (int o = 16; o > 0; o >>= 1) v += __shfl_xor_sync(0xffffffffu, v, o);
    return v;
}

__device__ __forceinline__ float dot4(float4 a, float4 b, float acc) {
    acc = fmaf(a.x, b.x, acc);
    acc = fmaf(a.y, b.y, acc);
    acc = fmaf(a.z, b.z, acc);
    acc = fmaf(a.w, b.w, acc);
    return acc;
}

__device__ __forceinline__ int ld_acq(const int* p) {
    int v;
    asm volatile("ld.acquire.gpu.u32 %0, [%1];" : "=r"(v) : "l"(p) : "memory");
    return v;
}
__device__ __forceinline__ void st_rel(int* p, int v) {
    asm volatile("st.release.gpu.u32 [%0], %1;" :: "l"(p), "r"(v) : "memory");
}

__global__ __launch_bounds__(128) void hawkes_fused(
    const int* __restrict__ ids, const float* __restrict__ times,
    const float* __restrict__ emb, const float* __restrict__ u_table,
    const float* __restrict__ beta, float* __restrict__ out)
{
    const int bc   = blockIdx.x;
    const int b    = bc >> 6;          // batch
    const int c    = bc & 63;          // chunk
    const int tid  = threadIdx.x;
    const int lane = tid & 31;
    const int warp = tid >> 5;

    __shared__ float sE[CHUNK][68];       // E rows, padded
    __shared__ float sw[CHUNK];           // exp(ab*t_j)
    __shared__ float sme[CHUNK];          // exp(-ab*t_j)
    __shared__ float svw[CHUNK];          // 1 - exp(-ab*(tlast-t_j))
    __shared__ float su[CHUNK];           // |u_j|
    __shared__ float spb[DD];             // exclusive cross-chunk prefix P (reused for final reduce)
    __shared__ float sP[4][CHUNK];        // phase-C d-slice partials
    __shared__ float spfP[8][DD];         // 8-way prefix partials
    __shared__ float spfE[8][DD];         // 8-way Et partials (c==0 only)
    __shared__ float spfV[8][DD];         // 8-way Vt partials (c==0 only)
    __shared__ float sb0[DD], sb1[DD], sb2[DD];
    __shared__ float sbase[2];
    __shared__ int   sid[CHUNK];
    __shared__ int   sgen;
    __shared__ int   slast;

    const float ab    = fabsf(beta[0]);
    const int   base  = b * LL + c * CHUNK;
    const float tlast = times[b * LL + LL - 1] * 1e-4f;

    // ---- gen from my OWN flag's pre-launch value (only this block writes it) ----
    if (tid == 0) sgen = g_flagA[b][c] + 1;

    // ---- init: ids, times, per-event scalars ----
    if (tid < CHUNK) {
        int id = ids[base + tid];
        sid[tid] = id;
        float tj = times[base + tid] * 1e-4f;
        float w  = __expf(ab * tj);
        sw[tid]  = w;
        sme[tid] = __expf(-ab * tj);
        svw[tid] = 1.0f - __expf(-ab * tlast) * w;
        su[tid]  = fabsf(u_table[id]);
    }
    __syncthreads();
    const int gen = sgen;

    // ---- gather E + per-chunk sums (thread = (d, g), g-half of j range) ----
    const int d = tid & 63, g = tid >> 6;
    float cs = 0.f, es = 0.f, vs = 0.f;
#pragma unroll
    for (int jj = 0; jj < 16; ++jj) {
        int j = g * 16 + jj;
        float e = emb[(long)sid[j] * DD + d];
        sE[j][d] = e;
        cs = fmaf(e, sw[j], cs);
        es += e;
        vs = fmaf(e, svw[j], vs);
    }
    if (g == 1) { sb0[d] = cs; sb1[d] = es; sb2[d] = vs; }
    __syncthreads();
    if (g == 0) {
        g_csum[b][c][d] = cs + sb0[d];
        g_esum[b][c][d] = es + sb1[d];
        g_vsum[b][c][d] = vs + sb2[d];
    }
    if (warp == 0) {
        float uv = warp_sum(su[lane]);
        if (lane == 0) g_usum[b][c] = uv;
    }

    // ---- publish flag (release orders all prior writes via the barrier) ----
    __syncthreads();
    if (tid == 0) st_rel(&g_flagA[b][c], gen);

    // ---- fine-grained wait: block c needs only chunks < c (c==0 needs all for base term) ----
    const int pollN = (c == 0) ? NCHUNK : c;
    if (tid < pollN) {
        const int* fp = &g_flagA[b][tid];
        while (ld_acq(fp) < gen) { }
    }
    __syncthreads();

    // ---- vectorized exclusive prefix: thread = (cp8 = tid>>4, float4 at d4) ----
    const int cp8 = tid >> 4;
    const int d4  = (tid & 15) * 4;
    {
        float4 acc = make_float4(0.f, 0.f, 0.f, 0.f);
        for (int cp = cp8; cp < c; cp += 8) {
            float4 v = *reinterpret_cast<const float4*>(&g_csum[b][cp][d4]);
            acc.x += v.x; acc.y += v.y; acc.z += v.z; acc.w += v.w;
        }
        *reinterpret_cast<float4*>(&spfP[cp8][d4]) = acc;
    }
    if (c == 0) {   // block (b,0): totals for the integral/base term
        float4 ae = make_float4(0.f, 0.f, 0.f, 0.f);
        float4 av = make_float4(0.f, 0.f, 0.f, 0.f);
        for (int cp = cp8; cp < NCHUNK; cp += 8) {
            float4 ve = *reinterpret_cast<const float4*>(&g_esum[b][cp][d4]);
            float4 vv = *reinterpret_cast<const float4*>(&g_vsum[b][cp][d4]);
            ae.x += ve.x; ae.y += ve.y; ae.z += ve.z; ae.w += ve.w;
            av.x += vv.x; av.y += vv.y; av.z += vv.z; av.w += vv.w;
        }
        *reinterpret_cast<float4*>(&spfE[cp8][d4]) = ae;
        *reinterpret_cast<float4*>(&spfV[cp8][d4]) = av;
    }
    __syncthreads();
    if (tid < DD) {
        float s = 0.f;
#pragma unroll
        for (int k = 0; k < 8; ++k) s += spfP[k][tid];
        spb[tid] = s;
    }
    if (c == 0) {
        float bval = 0.f;
        if (tid < DD) {
            float et = 0.f, vt = 0.f;
#pragma unroll
            for (int k = 0; k < 8; ++k) { et += spfE[k][tid]; vt += spfV[k][tid]; }
            float horizon = (times[b * LL + LL - 1] - times[b * LL + 1]) * 1e-4f;
            bval = et * vt + horizon * g_usum[b][tid];
        }
        if (warp < 2) {
            float s = warp_sum(bval);
            if (lane == 0) sbase[warp] = s;
        }
    }
    __syncthreads();
    if (c == 0 && tid == 0) g_base[b] = sbase[0] + sbase[1];

    // ---- phase C: dp_i = e_i·P + sum_{j<i} w_j (e_i·e_j), 4 warps = 4 D-slices ----
    {
        const int i = lane, q = warp;
        const float4* erow = reinterpret_cast<const float4*>(&sE[i][0]) + q * 4;
        float4 a0 = erow[0], a1 = erow[1], a2 = erow[2], a3 = erow[3];
        const float4* pb = reinterpret_cast<const float4*>(spb) + q * 4;
        float part = 0.f;
        part = dot4(a0, pb[0], part);
        part = dot4(a1, pb[1], part);
        part = dot4(a2, pb[2], part);
        part = dot4(a3, pb[3], part);
#pragma unroll
        for (int j = 0; j < CHUNK; ++j) {
            const float4* ej = reinterpret_cast<const float4*>(&sE[j][0]) + q * 4;
            float s = 0.f;
            s = dot4(a0, ej[0], s);
            s = dot4(a1, ej[1], s);
            s = dot4(a2, ej[2], s);
            s = dot4(a3, ej[3], s);
            if (j < i) part = fmaf(sw[j], s, part);   // strict lower triangle
        }
        sP[q][i] = part;
    }
    __syncthreads();
    if (warp == 0) {
        float dp  = sP[0][lane] + sP[1][lane] + sP[2][lane] + sP[3][lane];
        float s1  = ab * sme[lane] * dp;
        float lam = fabsf(s1 + su[lane]) + 1e-6f;
        float v   = -__logf(lam);
        v = warp_sum(v);
        if (lane == 0) g_accv[b][c] = v;
    }

    // ---- completion ticket; last block per batch reduces deterministically ----
    __threadfence();
    __syncthreads();
    if (tid == 0) {
        int t = atomicAdd(&g_cntB[b], 1);
        slast = ((t & 63) == 63) ? 1 : 0;
    }
    __syncthreads();
    if (slast) {
        __threadfence();
        if (tid < NCHUNK) spb[tid] = __ldcg(&g_accv[b][tid]);
        __syncthreads();
        if (tid == 0) {
            float s = 0.f;
            for (int k = 0; k < NCHUNK; ++k) s += spb[k];   // fixed order -> deterministic
            out[b] = s + __ldcg(&g_base[b]);
        }
    }
}

extern "C" void kernel_launch(void* const* d_in, const int* in_sizes, int n_in,
                              void* d_out, int out_size) {
    const int*   ids   = (const int*)  d_in[0];
    const float* times = (const float*)d_in[1];
    // d_in[2] = mask (all ones, unused)
    const float* emb   = (const float*)d_in[3];
    const float* ut    = (const float*)d_in[4];
    const float* beta  = (const float*)d_in[5];
    float* out = (float*)d_out;

    hawkes_fused<<<BB * NCHUNK, 128>>>(ids, times, emb, ut, beta, out);
}

// round 5
// speedup vs baseline: 1.6571x; 1.1467x over previous
#include <cuda_runtime.h>
#include <math.h>

#define BB 4
#define LL 2048
#define DD 64
#define CHUNK 32
#define NGRP 32          // groups per batch (2 chunks per group)
#define GEVT 64          // events per group

// Scratch (no cudaMalloc allowed). Flags/counters are monotonic across launches (never reset).
__device__ float g_gcsum[BB][NGRP][DD];
__device__ float g_gesum[BB][NGRP][DD];
__device__ float g_gvsum[BB][NGRP][DD];
__device__ float g_gusum[BB][NGRP];
__device__ float g_accv[BB][NGRP];
__device__ float g_base[BB];
__device__ int   g_flag[BB][NGRP];   // +1 per launch (launch-relative generations)
__device__ int   g_cnt[BB];          // +NGRP per launch

__device__ __forceinline__ float warp_sum(float v) {
#pragma unroll
    for (int o = 16; o > 0; o >>= 1) v += __shfl_xor_sync(0xffffffffu, v, o);
    return v;
}

__device__ __forceinline__ float dot4(float4 a, float4 b, float acc) {
    acc = fmaf(a.x, b.x, acc);
    acc = fmaf(a.y, b.y, acc);
    acc = fmaf(a.z, b.z, acc);
    acc = fmaf(a.w, b.w, acc);
    return acc;
}

__device__ __forceinline__ int ld_acq(const int* p) {
    int v;
    asm volatile("ld.acquire.gpu.u32 %0, [%1];" : "=r"(v) : "l"(p) : "memory");
    return v;
}
__device__ __forceinline__ void st_rel(int* p, int v) {
    asm volatile("st.release.gpu.u32 [%0], %1;" :: "l"(p), "r"(v) : "memory");
}

__global__ __launch_bounds__(256) void hawkes_fused(
    const int* __restrict__ ids, const float* __restrict__ times,
    const float* __restrict__ emb, const float* __restrict__ u_table,
    const float* __restrict__ beta, float* __restrict__ out)
{
    const int bg   = blockIdx.x;
    const int b    = bg >> 5;          // batch
    const int cg   = bg & 31;          // group (2 chunks)
    const int tid  = threadIdx.x;
    const int lane = tid & 31;
    const int warp = tid >> 5;
    const int half = tid >> 7;         // chunk within group (phase A)
    const int ht   = tid & 127;
    const int d    = ht & 63, g = ht >> 6;

    __shared__ float sE[GEVT][68];             // both chunks' E rows, padded
    __shared__ float sw[GEVT], sme[GEVT], svw[GEVT];
    __shared__ float sb0[2][DD], sb1[2][DD], sb2[2][DD];
    __shared__ float sCs[2][DD], sEs[2][DD], sVs[2][DD];   // per-chunk totals
    __shared__ float spb[2][DD];               // per-chunk exclusive prefix
    __shared__ float sP[8][CHUNK];             // phase-C d-slice partials
    __shared__ float spf[16][DD];              // 16-way prefix partials (reused in tail)
    __shared__ float spfE[16][DD], spfV[16][DD];
    __shared__ float sures[2], slog[2], sbase[2];
    __shared__ int   sid[GEVT];
    __shared__ int   sgen, slast;

    const float ab = fabsf(beta[0]);
    if (tid == 0) sgen = g_flag[b][cg] + 1;

    // ---- init (warps 0 and 4 handle their own chunk): ids, per-event scalars.
    // u_table gather result stays in a REGISTER, unconsumed until the log phase,
    // so its DRAM trip does NOT serialize before the first barrier.
    float u_reg = 0.f;
    if ((warp & 3) == 0) {
        const int ch   = warp >> 2;
        const int gidx = b * LL + cg * GEVT + ch * CHUNK + lane;
        int id = ids[gidx];
        sid[ch * CHUNK + lane] = id;
        float tj    = times[gidx] * 1e-4f;
        float tlast = times[b * LL + LL - 1] * 1e-4f;
        float w = __expf(ab * tj);
        sw [ch * CHUNK + lane] = w;
        sme[ch * CHUNK + lane] = __expf(-ab * tj);
        svw[ch * CHUNK + lane] = 1.0f - __expf(-ab * tlast) * w;
        u_reg = u_table[id];               // outstanding load, no consume here
    }
    __syncthreads();
    const int gen = sgen;

    // ---- gather E + per-chunk sums (each 128-thread half = one chunk) ----
    float cs = 0.f, es = 0.f, vs = 0.f;
#pragma unroll
    for (int jj = 0; jj < 16; ++jj) {
        int j = half * CHUNK + g * 16 + jj;
        float e = emb[(long)sid[j] * DD + d];
        sE[j][d] = e;
        cs = fmaf(e, sw[j], cs);
        es += e;
        vs = fmaf(e, svw[j], vs);
    }
    if (g == 1) { sb0[half][d] = cs; sb1[half][d] = es; sb2[half][d] = vs; }
    __syncthreads();
    if (g == 0) {
        sCs[half][d] = cs + sb0[half][d];
        sEs[half][d] = es + sb1[half][d];
        sVs[half][d] = vs + sb2[half][d];
    }
    if ((warp & 3) == 0) {
        float uv = warp_sum(fabsf(u_reg));
        if (lane == 0) sures[warp >> 2] = uv;
    }
    __syncthreads();

    // ---- publish group sums + flag (release after CTA barrier) ----
    if (tid < DD) {
        g_gcsum[b][cg][tid] = sCs[0][tid] + sCs[1][tid];
        g_gesum[b][cg][tid] = sEs[0][tid] + sEs[1][tid];
        g_gvsum[b][cg][tid] = sVs[0][tid] + sVs[1][tid];
    }
    __syncthreads();
    if (tid == 0) {
        g_gusum[b][cg] = sures[0] + sures[1];
        st_rel(&g_flag[b][cg], gen);
    }

    // ---- fine-grained wait: group cg needs groups < cg (cg==0 needs all for base) ----
    const int pollN = (cg == 0) ? NGRP : cg;
    if (tid < pollN) {
        const int* fp = &g_flag[b][tid];
        while (ld_acq(fp) < gen) { }
    }
    __syncthreads();

    // ---- vectorized exclusive group prefix: thread = (i16 = tid>>4, float4 at d4) ----
    const int i16 = tid >> 4;
    const int d4  = (tid & 15) * 4;
    {
        float4 acc = make_float4(0.f, 0.f, 0.f, 0.f);
        for (int cp = i16; cp < cg; cp += 16) {
            float4 v = *reinterpret_cast<const float4*>(&g_gcsum[b][cp][d4]);
            acc.x += v.x; acc.y += v.y; acc.z += v.z; acc.w += v.w;
        }
        *reinterpret_cast<float4*>(&spf[i16][d4]) = acc;
    }
    if (cg == 0) {   // group 0: totals for the integral/base term
        float4 ae = make_float4(0.f, 0.f, 0.f, 0.f);
        float4 av = make_float4(0.f, 0.f, 0.f, 0.f);
        for (int cp = i16; cp < NGRP; cp += 16) {
            float4 ve = *reinterpret_cast<const float4*>(&g_gesum[b][cp][d4]);
            float4 vv = *reinterpret_cast<const float4*>(&g_gvsum[b][cp][d4]);
            ae.x += ve.x; ae.y += ve.y; ae.z += ve.z; ae.w += ve.w;
            av.x += vv.x; av.y += vv.y; av.z += vv.z; av.w += vv.w;
        }
        *reinterpret_cast<float4*>(&spfE[i16][d4]) = ae;
        *reinterpret_cast<float4*>(&spfV[i16][d4]) = av;
    }
    __syncthreads();
    if (tid < DD) {
        float s = 0.f;
#pragma unroll
        for (int k = 0; k < 16; ++k) s += spf[k][tid];
        spb[0][tid] = s;                       // chunk 0: group prefix
        spb[1][tid] = s + sCs[0][tid];         // chunk 1: + chunk 0 csum (from smem)
    }
    if (cg == 0) {
        float bval = 0.f;
        if (tid < DD) {
            float et = 0.f, vt = 0.f;
#pragma unroll
            for (int k = 0; k < 16; ++k) { et += spfE[k][tid]; vt += spfV[k][tid]; }
            bval = et * vt;
            if (tid < NGRP) {
                float horizon = (times[b * LL + LL - 1] - times[b * LL + 1]) * 1e-4f;
                bval += horizon * __ldcg(&g_gusum[b][tid]);
            }
        }
        if (warp < 2) {
            float s = warp_sum(bval);
            if (lane == 0) sbase[warp] = s;
        }
    }
    __syncthreads();
    if (cg == 0 && tid == 0) g_base[b] = sbase[0] + sbase[1];

    // ---- phase C: dp_i = e_i·P + sum_{j<i} w_j (e_i·e_j); 8 warps = 2 chunks × 4 D-slices
    {
        const int ch = warp >> 2, q = warp & 3, i = lane;
        const float4* erow = reinterpret_cast<const float4*>(&sE[ch * CHUNK + i][0]) + q * 4;
        float4 a0 = erow[0], a1 = erow[1], a2 = erow[2], a3 = erow[3];
        const float4* pb = reinterpret_cast<const float4*>(&spb[ch][0]) + q * 4;
        float part = 0.f;
        part = dot4(a0, pb[0], part);
        part = dot4(a1, pb[1], part);
        part = dot4(a2, pb[2], part);
        part = dot4(a3, pb[3], part);
#pragma unroll
        for (int j = 0; j < CHUNK; ++j) {
            const float4* ej = reinterpret_cast<const float4*>(&sE[ch * CHUNK + j][0]) + q * 4;
            float s = 0.f;
            s = dot4(a0, ej[0], s);
            s = dot4(a1, ej[1], s);
            s = dot4(a2, ej[2], s);
            s = dot4(a3, ej[3], s);
            if (j < i) part = fmaf(sw[ch * CHUNK + j], s, part);   // strict lower triangle
        }
        sP[warp][i] = part;
    }
    __syncthreads();
    if ((warp & 3) == 0) {
        const int ch = warp >> 2;
        float dp  = sP[ch * 4][lane] + sP[ch * 4 + 1][lane]
                  + sP[ch * 4 + 2][lane] + sP[ch * 4 + 3][lane];
        float s1  = ab * sme[ch * CHUNK + lane] * dp;
        float lam = fabsf(s1 + fabsf(u_reg)) + 1e-6f;
        float v   = warp_sum(-__logf(lam));
        if (lane == 0) slog[ch] = v;
    }
    __syncthreads();

    // ---- completion ticket; last group per batch reduces deterministically ----
    if (tid == 0) {
        g_accv[b][cg] = slog[0] + slog[1];
        __threadfence();
        int t = atomicAdd(&g_cnt[b], 1);
        slast = ((t & (NGRP - 1)) == (NGRP - 1)) ? 1 : 0;
    }
    __syncthreads();
    if (slast) {
        __threadfence();
        if (tid < NGRP) spf[0][tid] = __ldcg(&g_accv[b][tid]);
        __syncthreads();
        if (tid == 0) {
            float s = 0.f;
            for (int k = 0; k < NGRP; ++k) s += spf[0][k];   // fixed order -> deterministic
            out[b] = s + __ldcg(&g_base[b]);
        }
    }
}

extern "C" void kernel_launch(void* const* d_in, const int* in_sizes, int n_in,
                              void* d_out, int out_size) {
    const int*   ids   = (const int*)  d_in[0];
    const float* times = (const float*)d_in[1];
    // d_in[2] = mask (all ones, unused)
    const float* emb   = (const float*)d_in[3];
    const float* ut    = (const float*)d_in[4];
    const float* beta  = (const float*)d_in[5];
    float* out = (float*)d_out;

    hawkes_fused<<<BB * NGRP, 256>>>(ids, times, emb, ut, beta, out);
}

// round 6
// speedup vs baseline: 1.9348x; 1.1676x over previous
#include <cuda_runtime.h>
#include <math.h>

#define BB 4
#define LL 2048
#define DD 64
#define CHUNK 32
#define NGRP 16          // groups per batch (4 chunks per group)
#define GEVT 128         // events per group

// Scratch (no cudaMalloc allowed). Flags/counters are monotonic across launches (never reset).
__device__ float g_gcsum[BB][NGRP][DD];
__device__ float g_gesum[BB][NGRP][DD];
__device__ float g_gvsum[BB][NGRP][DD];
__device__ float g_gusum[BB][NGRP];
__device__ float g_accv[BB][NGRP];
__device__ int   g_flag[BB][NGRP];   // +1 per launch (launch-relative generations)
__device__ int   g_cnt[BB];          // +NGRP per launch

__device__ __forceinline__ float warp_sum(float v) {
#pragma unroll
    for (int o = 16; o > 0; o >>= 1) v += __shfl_xor_sync(0xffffffffu, v, o);
    return v;
}

__device__ __forceinline__ float dot4(float4 a, float4 b, float acc) {
    acc = fmaf(a.x, b.x, acc);
    acc = fmaf(a.y, b.y, acc);
    acc = fmaf(a.z, b.z, acc);
    acc = fmaf(a.w, b.w, acc);
    return acc;
}

__device__ __forceinline__ int ld_acq(const int* p) {
    int v;
    asm volatile("ld.acquire.gpu.u32 %0, [%1];" : "=r"(v) : "l"(p) : "memory");
    return v;
}
__device__ __forceinline__ void st_rel(int* p, int v) {
    asm volatile("st.release.gpu.u32 [%0], %1;" :: "l"(p), "r"(v) : "memory");
}

__global__ __launch_bounds__(512) void hawkes_fused(
    const int* __restrict__ ids, const float* __restrict__ times,
    const float* __restrict__ emb, const float* __restrict__ u_table,
    const float* __restrict__ beta, float* __restrict__ out)
{
    const int bg   = blockIdx.x;
    const int b    = bg >> 4;          // batch
    const int cg   = bg & 15;          // group (4 chunks)
    const int tid  = threadIdx.x;
    const int lane = tid & 31;
    const int warp = tid >> 5;         // 0..15
    const int half = tid >> 7;         // chunk within group (phase A), 0..3
    const int ht   = tid & 127;
    const int d    = ht & 63, g = ht >> 6;

    __shared__ float sE[GEVT][68];                 // 4 chunks' E rows, padded
    __shared__ float sw[GEVT], sme[GEVT], svw[GEVT];
    __shared__ float sb0[4][DD], sb1[4][DD], sb2[4][DD];
    __shared__ float sCs[4][DD], sEs[4][DD], sVs[4][DD];   // per-chunk totals
    __shared__ float spb[4][DD];                   // per-chunk exclusive prefix
    __shared__ float sP[16][CHUNK];                // phase-C d-slice partials
    __shared__ float spf[16][DD];                  // 16-way prefix partials (tail reuse)
    __shared__ float spfE[16][DD], spfV[16][DD];   // tail base-term partials
    __shared__ float sures[4], slog[4], sbase[2];
    __shared__ int   sid[GEVT];
    __shared__ int   slast;

    const float ab  = fabsf(beta[0]);
    const int   gen = g_flag[b][cg] + 1;   // own flag's pre-launch value (broadcast load)

    // ---- init (warps 0,4,8,12 -> one chunk each): ids, per-event scalars.
    // u_table result stays in a register, unconsumed until the log phase, so its
    // memory trip does not serialize before the first barrier.
    float u_reg = 0.f;
    if ((warp & 3) == 0) {
        const int ch   = warp >> 2;
        const int gidx = b * LL + cg * GEVT + ch * CHUNK + lane;
        int id = ids[gidx];
        sid[ch * CHUNK + lane] = id;
        float tj    = times[gidx] * 1e-4f;
        float tlast = times[b * LL + LL - 1] * 1e-4f;
        float w = __expf(ab * tj);
        sw [ch * CHUNK + lane] = w;
        sme[ch * CHUNK + lane] = __expf(-ab * tj);
        svw[ch * CHUNK + lane] = 1.0f - __expf(-ab * tlast) * w;
        u_reg = u_table[id];
    }
    __syncthreads();

    // ---- gather E + per-chunk sums (each 128-thread quarter = one chunk) ----
    float cs = 0.f, es = 0.f, vs = 0.f;
#pragma unroll
    for (int jj = 0; jj < 16; ++jj) {
        int j = half * CHUNK + g * 16 + jj;
        float e = emb[(long)sid[j] * DD + d];
        sE[j][d] = e;
        cs = fmaf(e, sw[j], cs);
        es += e;
        vs = fmaf(e, svw[j], vs);
    }
    if (g == 1) { sb0[half][d] = cs; sb1[half][d] = es; sb2[half][d] = vs; }
    if ((warp & 3) == 0) {
        float uv = warp_sum(fabsf(u_reg));
        if (lane == 0) sures[warp >> 2] = uv;
    }
    __syncthreads();
    if (g == 0) {
        sCs[half][d] = cs + sb0[half][d];
        sEs[half][d] = es + sb1[half][d];
        sVs[half][d] = vs + sb2[half][d];
    }
    __syncthreads();

    // ---- publish group sums + flag ----
    if (tid < DD) {
        g_gcsum[b][cg][tid] = sCs[0][tid] + sCs[1][tid] + sCs[2][tid] + sCs[3][tid];
        g_gesum[b][cg][tid] = sEs[0][tid] + sEs[1][tid] + sEs[2][tid] + sEs[3][tid];
        g_gvsum[b][cg][tid] = sVs[0][tid] + sVs[1][tid] + sVs[2][tid] + sVs[3][tid];
    }
    __syncthreads();
    if (tid == 0) {
        g_gusum[b][cg] = sures[0] + sures[1] + sures[2] + sures[3];
        st_rel(&g_flag[b][cg], gen);
    }

    // ---- fine-grained wait: group cg needs only groups < cg ----
    if (tid < cg) {
        const int* fp = &g_flag[b][tid];
        while (ld_acq(fp) < gen) { }
    }
    __syncthreads();

    // ---- vectorized exclusive group prefix: thread = (i16 = tid>>4, float4 at d4) ----
    const int i16 = tid >> 4;      // 0..31 (only 0..15 used per stride)
    const int d4  = (tid & 15) * 4;
    if (tid < 256) {
        float4 acc = make_float4(0.f, 0.f, 0.f, 0.f);
        for (int cp = i16; cp < cg; cp += 16) {
            float4 v = *reinterpret_cast<const float4*>(&g_gcsum[b][cp][d4]);
            acc.x += v.x; acc.y += v.y; acc.z += v.z; acc.w += v.w;
        }
        *reinterpret_cast<float4*>(&spf[i16][d4]) = acc;
    }
    __syncthreads();
    if (tid < DD) {
        float s = 0.f;
#pragma unroll
        for (int k = 0; k < 16; ++k) s += spf[k][tid];
        spb[0][tid] = s;
        spb[1][tid] = s + sCs[0][tid];
        spb[2][tid] = s + sCs[0][tid] + sCs[1][tid];
        spb[3][tid] = s + sCs[0][tid] + sCs[1][tid] + sCs[2][tid];
    }
    __syncthreads();

    // ---- phase C: dp_i = e_i·P + sum_{j<i} w_j (e_i·e_j); 16 warps = 4 chunks × 4 D-slices
    {
        const int ch = warp >> 2, q = warp & 3, i = lane;
        const float4* erow = reinterpret_cast<const float4*>(&sE[ch * CHUNK + i][0]) + q * 4;
        float4 a0 = erow[0], a1 = erow[1], a2 = erow[2], a3 = erow[3];
        const float4* pb = reinterpret_cast<const float4*>(&spb[ch][0]) + q * 4;
        float part = 0.f;
        part = dot4(a0, pb[0], part);
        part = dot4(a1, pb[1], part);
        part = dot4(a2, pb[2], part);
        part = dot4(a3, pb[3], part);
#pragma unroll
        for (int j = 0; j < CHUNK; ++j) {
            const float4* ej = reinterpret_cast<const float4*>(&sE[ch * CHUNK + j][0]) + q * 4;
            float s = 0.f;
            s = dot4(a0, ej[0], s);
            s = dot4(a1, ej[1], s);
            s = dot4(a2, ej[2], s);
            s = dot4(a3, ej[3], s);
            if (j < i) part = fmaf(sw[ch * CHUNK + j], s, part);   // strict lower triangle
        }
        sP[warp][i] = part;
    }
    __syncthreads();
    if ((warp & 3) == 0) {
        const int ch = warp >> 2;
        float dp  = sP[ch * 4][lane] + sP[ch * 4 + 1][lane]
                  + sP[ch * 4 + 2][lane] + sP[ch * 4 + 3][lane];
        float s1  = ab * sme[ch * CHUNK + lane] * dp;
        float lam = fabsf(s1 + fabsf(u_reg)) + 1e-6f;
        float v   = warp_sum(-__logf(lam));
        if (lane == 0) slog[ch] = v;
    }
    __syncthreads();

    // ---- completion ticket; LAST group per batch computes base term + reduces ----
    if (tid == 0) {
        g_accv[b][cg] = slog[0] + slog[1] + slog[2] + slog[3];
        __threadfence();
        int t = atomicAdd(&g_cnt[b], 1);
        slast = ((t & (NGRP - 1)) == (NGRP - 1)) ? 1 : 0;
    }
    __syncthreads();
    if (slast) {
        __threadfence();
        // Et/Vt totals over all groups (published long before tickets)
        if (tid < 256) {   // i16 = 0..15, one group each
            float4 ve = *reinterpret_cast<const float4*>(&g_gesum[b][i16][d4]);
            float4 vv = *reinterpret_cast<const float4*>(&g_gvsum[b][i16][d4]);
            *reinterpret_cast<float4*>(&spfE[i16][d4]) = ve;
            *reinterpret_cast<float4*>(&spfV[i16][d4]) = vv;
        }
        if (tid < NGRP) spf[0][tid] = __ldcg(&g_accv[b][tid]);
        __syncthreads();
        float bval = 0.f;
        if (tid < DD) {
            float et = 0.f, vt = 0.f;
#pragma unroll
            for (int k = 0; k < 16; ++k) { et += spfE[k][tid]; vt += spfV[k][tid]; }
            bval = et * vt;
            if (tid < NGRP) {
                float horizon = (times[b * LL + LL - 1] - times[b * LL + 1]) * 1e-4f;
                bval += horizon * __ldcg(&g_gusum[b][tid]);
            }
        }
        if (warp < 2) {
            float s = warp_sum(bval);
            if (lane == 0) sbase[warp] = s;
        }
        __syncthreads();
        if (tid == 0) {
            float s = 0.f;
            for (int k = 0; k < NGRP; ++k) s += spf[0][k];   // fixed order -> deterministic
            out[b] = s + sbase[0] + sbase[1];
        }
    }
}

extern "C" void kernel_launch(void* const* d_in, const int* in_sizes, int n_in,
                              void* d_out, int out_size) {
    const int*   ids   = (const int*)  d_in[0];
    const float* times = (const float*)d_in[1];
    // d_in[2] = mask (all ones, unused)
    const float* emb   = (const float*)d_in[3];
    const float* ut    = (const float*)d_in[4];
    const float* beta  = (const float*)d_in[5];
    float* out = (float*)d_out;

    hawkes_fused<<<BB * NGRP, 512>>>(ids, times, emb, ut, beta, out);
}